// round 16
// baseline (speedup 1.0000x reference)
#include <cuda_runtime.h>
#include <stdint.h>

#define HH 721
#define WW 1440
#define NPTS (HH*WW)
#define NQ4  (NPTS/4)
#define SEGS ((NQ4 + 1023) / 1024)     // 254 segments of 1024 q per batch
#define BB 16
#define CC 4
#define DD 256
#define NV 12
#define NCHUNK 6
#define CHW 240
#define MEGA_BLOCKS 148
#define GNN_BLOCKS 32
#define VMAP_WARPS (GNN_BLOCKS*24 + (MEGA_BLOCKS-GNN_BLOCKS)*32)   // 4480
#define PI_D 3.141592653589793
#define TWOPI_D (2.0*PI_D)

static __device__ double        g_dla2d[NV][HH];
static __device__ double        g_dlo2d[NV][WW];
static __device__ float         g_dla2f[NV][HH];
static __device__ float         g_dlo2f[NV][WW];
static __device__ unsigned int  g_v2gi[NV];
static __device__ unsigned char g_vmap[NPTS];
static __device__ float         g_nodes[BB*NV*CC];
static __device__ float         g_hn[BB*NV*DD];
static __device__ volatile unsigned g_bar  = 0;   // ticket barrier (monotonic, never reset)
static __device__ volatile unsigned g_bar2 = 0;   // GNN ticket barrier (monotonic)

__constant__ signed char c_vcode[NV][3] = {
    {-1,2,0},{1,2,0},{-1,-2,0},{1,-2,0},{0,-1,2},{0,1,2},
    {0,-1,-2},{0,1,-2},{2,0,-1},{2,0,1},{-2,0,-1},{-2,0,1}};
__constant__ int c_nbr[NV][5] = {
    {11,5,1,7,10},{0,5,7,9,8},{11,10,3,4,6},{9,4,2,6,8},
    {5,11,3,9,2},{0,11,1,9,4},{10,7,3,2,8},{0,1,10,6,8},
    {7,1,3,6,9},{1,5,3,4,8},{0,7,11,2,6},{0,5,10,2,4}};

// named barrier for the 256 GNN threads (warps 0-7) of a block
#define NB1() asm volatile("bar.sync 1, 256;" ::: "memory")

// monotonic ticket barrier over all MEGA_BLOCKS (replay-safe: no reset needed)
__device__ __forceinline__ void barrier_all() {
    __syncthreads();
    if (threadIdx.x == 0) {
        __threadfence();
        unsigned old = atomicAdd((unsigned*)&g_bar, 1u);
        unsigned target = (old / MEGA_BLOCKS + 1u) * MEGA_BLOCKS;
        while (g_bar < target) { }
        __threadfence();
    }
    __syncthreads();
}
// monotonic ticket barrier over the 32 GNN blocks (GNN warps only)
__device__ __forceinline__ void barrier_gnn() {
    NB1();
    if (threadIdx.x == 0) {
        __threadfence();
        unsigned old = atomicAdd((unsigned*)&g_bar2, 1u);
        unsigned target = (old / GNN_BLOCKS + 1u) * GNN_BLOCKS;
        while (g_bar2 < target) { }
        __threadfence();
    }
    NB1();
}

// ---- THE kernel: P1 tables | barrier | GNN (blocks 0-31, warps 0-7) ∥ vmap (all other
//      warps, warp-autonomous) | barrier | all-chip scatter. One launch per call. ----
__global__ void __launch_bounds__(1024) k_mega(const float* __restrict__ x,
                                               const float* __restrict__ Win,
                                               const float* __restrict__ bin,
                                               const float* __restrict__ Wlayers,
                                               const float* __restrict__ bl,
                                               const float* __restrict__ Wout,
                                               const float* __restrict__ bout,
                                               float* __restrict__ out) {
    int bid = blockIdx.x, t = threadIdx.x;
    int w = t >> 5, lane = t & 31;
    __shared__ __align__(16) float h_s[NV * DD];
    __shared__ __align__(16) float agg_s[NV * DD];
    __shared__ float  s_sval[BB * NV * CC];     // scatter LUT (768 floats)
    __shared__ double s_vll[2];
    __shared__ double s_rv[8];
    __shared__ int    s_ri[8];
    __shared__ int    s_best[2];

    // ================= P1: per-vertex f64 tables + separable argmin (blocks 0-11) =========
    double bla = 1.0e300, blo = 1.0e300; int bia = 0, bio = 0;
    if (bid < NV) {
        int v = bid;
        if (t == 0) {
            float phi = (float)((1.0 + sqrt(5.0)) * 0.5);
            float c[3];
#pragma unroll
            for (int k = 0; k < 3; k++) {
                int cd = c_vcode[v][k];
                float m = (cd == 2 || cd == -2) ? phi : 1.0f;
                c[k] = (cd == 0) ? 0.0f : (cd < 0 ? -m : m);
            }
            float n2 = __fadd_rn(__fadd_rn(__fmul_rn(c[0],c[0]), __fmul_rn(c[1],c[1])),
                                 __fmul_rn(c[2],c[2]));
            float nrm = __fsqrt_rn(n2);
            float xx = __fdiv_rn(c[0],nrm), yy = __fdiv_rn(c[1],nrm), zz = __fdiv_rn(c[2],nrm);
            float s = __fsqrt_rn(__fsub_rn(1.0f, __fmul_rn(zz,zz)));
            s_vll[0] = (double)__fmul_rn(2.0f, atan2f(zz, __fadd_rn(1.0f, s)));  // XLA asin
            s_vll[1] = (double)atan2f(yy, xx);
        }
        __syncthreads();
        if (t < 256) {
            double vlat = s_vll[0], vlon = s_vll[1];
            double dla_s = __ddiv_rn(PI_D, 720.0);
            double dlo_s = __ddiv_rn(TWOPI_D, 1439.0);
            for (int li = t; li < HH; li += 256) {
                double lat = __dadd_rn(-(PI_D*0.5), __dmul_rn((double)li, dla_s));
                if (li == 360) lat = 1.0e-12;    // symmetry row pinned positive (validated)
                double dla = __dsub_rn(lat, vlat);
                double q = __dmul_rn(dla, dla);
                g_dla2d[v][li] = q;
                g_dla2f[v][li] = (float)q;
                if (q < bla) { bla = q; bia = li; }
            }
            for (int lj = t; lj < WW; lj += 256) {
                double lon = __dadd_rn(-PI_D, __dmul_rn((double)lj, dlo_s));
                double raw = __dadd_rn(__dsub_rn(lon, vlon), PI_D);
                double r = raw;
                if (raw >= TWOPI_D)   r = __dsub_rn(raw, TWOPI_D);
                else if (raw < 0.0)   r = __dadd_rn(raw, TWOPI_D);
                double dlo = __dsub_rn(r, PI_D);
                double q = __dmul_rn(dlo, dlo);
                g_dlo2d[v][lj] = q;
                g_dlo2f[v][lj] = (float)q;
                if (q < blo) { blo = q; bio = lj; }
            }
        }
        // separable v2g argmin (lex tie-break == first-index)
#pragma unroll
        for (int pass = 0; pass < 2; pass++) {
            if (t < 256) {
                double bv = pass ? blo : bla;
                int    bi = pass ? bio : bia;
#pragma unroll
                for (int off = 16; off > 0; off >>= 1) {
                    double ov = __shfl_down_sync(0xFFFFFFFFu, bv, off);
                    int    oi = __shfl_down_sync(0xFFFFFFFFu, bi, off);
                    if (ov < bv || (ov == bv && oi < bi)) { bv = ov; bi = oi; }
                }
                if (lane == 0) { s_rv[w] = bv; s_ri[w] = bi; }
            }
            __syncthreads();
            if (t < 8) {
                double bv = s_rv[t]; int bi = s_ri[t];
#pragma unroll
                for (int off = 4; off > 0; off >>= 1) {
                    double ov = __shfl_down_sync(0xFFu, bv, off);
                    int    oi = __shfl_down_sync(0xFFu, bi, off);
                    if (ov < bv || (ov == bv && oi < bi)) { bv = ov; bi = oi; }
                }
                if (t == 0) s_best[pass] = bi;
            }
            __syncthreads();
        }
        if (t == 0) g_v2gi[v] = (unsigned)(s_best[0] * WW + s_best[1]);
    }

    barrier_all();

    // ================= Phase 2: GNN (blocks 0-31, threads 0-255) ∥ vmap (rest) ============
    if (bid < GNN_BLOCKS && t < 256) {
        // ---- GNN, identical math to R11-R15; NB1 replaces __syncthreads ----
        int b = bid >> 1, half = bid & 1;
#pragma unroll
        for (int v = 0; v < NV; v++) {
            unsigned p = g_v2gi[v];
            int pi = p / WW, pj = p - pi * WW;
            const float* xb = x + ((long)(b * CC) * HH + pi) * WW + pj;
            float acc = __ldg(&bin[t]);
            acc = fmaf(__ldg(xb + 0L*HH*WW), __ldg(&Win[0*DD + t]), acc);
            acc = fmaf(__ldg(xb + 1L*HH*WW), __ldg(&Win[1*DD + t]), acc);
            acc = fmaf(__ldg(xb + 2L*HH*WW), __ldg(&Win[2*DD + t]), acc);
            acc = fmaf(__ldg(xb + 3L*HH*WW), __ldg(&Win[3*DD + t]), acc);
            h_s[v * DD + t] = acc;
        }
        NB1();

        int d  = half * 128 + (t & 127);
        int vb = (t >> 7) * 6;
        const float4* a4 = reinterpret_cast<const float4*>(agg_s);

        for (int l = 0; l < 4; l++) {
#pragma unroll
            for (int v = 0; v < NV; v++) {
                float s = h_s[c_nbr[v][0]*DD + t] + h_s[c_nbr[v][1]*DD + t]
                        + h_s[c_nbr[v][2]*DD + t] + h_s[c_nbr[v][3]*DD + t]
                        + h_s[c_nbr[v][4]*DD + t];
                agg_s[v * DD + t] = s * 0.2f;
            }
            NB1();

            const float* Wl = Wlayers + l * DD * DD;
            float acc[6] = {0.f, 0.f, 0.f, 0.f, 0.f, 0.f};
#pragma unroll 4
            for (int kq = 0; kq < DD/4; kq++) {
                float w0 = __ldg(Wl + (kq*4 + 0) * DD + d);
                float w1 = __ldg(Wl + (kq*4 + 1) * DD + d);
                float w2 = __ldg(Wl + (kq*4 + 2) * DD + d);
                float w3 = __ldg(Wl + (kq*4 + 3) * DD + d);
#pragma unroll
                for (int r = 0; r < 6; r++) {
                    float4 a = a4[(vb + r) * (DD/4) + kq];
                    acc[r] = fmaf(a.x, w0, fmaf(a.y, w1, fmaf(a.z, w2, fmaf(a.w, w3, acc[r]))));
                }
            }
            float bias = __ldg(&bl[l * DD + d]);
#pragma unroll
            for (int r = 0; r < 6; r++) {
                int v = vb + r;
                g_hn[(b * NV + v) * DD + d] = h_s[v * DD + d] + fmaxf(acc[r] + bias, 0.0f);
            }

            barrier_gnn();

            float4* h4 = reinterpret_cast<float4*>(h_s);
            const float4* gh4 = reinterpret_cast<const float4*>(g_hn + b * NV * DD);
#pragma unroll
            for (int idx = t; idx < NV * DD / 4; idx += 256) h4[idx] = gh4[idx];
            NB1();
        }

        // outproj: 48 (v,c) pairs over this block's 8 warps
#pragma unroll
        for (int r = 0; r < 3; r++) {
            int pair = half * 24 + w * 3 + r;
            int v = pair >> 2, c = pair & 3;
            float s = 0.f;
#pragma unroll
            for (int k = lane; k < DD; k += 32)
                s = fmaf(h_s[v * DD + k], __ldg(&Wout[k * CC + c]), s);
#pragma unroll
            for (int off = 16; off > 0; off >>= 1)
                s += __shfl_down_sync(0xFFFFFFFFu, s, off);
            if (lane == 0) g_nodes[(b * NV + v) * CC + c] = s + __ldg(&bout[c]);
        }
    } else {
        // ---- vmap: warp-autonomous (row, 240-chunk) units; R13-validated semantics ----
        int gw = (bid < GNN_BLOCKS) ? (bid * 24 + (w - 8))
                                    : (GNN_BLOCKS * 24 + (bid - GNN_BLOCKS) * 32 + w);
        for (int cid = gw; cid < HH * NCHUNK; cid += VMAP_WARPS) {
            int li = cid / NCHUNK, ch = cid - li * NCHUNK;
            float sa[NV];
#pragma unroll
            for (int v = 0; v < NV; v++) sa[v] = __ldg(&g_dla2f[v][li]);
            for (int o = lane; o < CHW; o += 32) {
                int lj = ch * CHW + o;
                // packed-key argmin: d2>0 -> int order == float order; 16-ulp mask (<=3e-5)
                // only perturbs margins < 1e-4 which all go to the exact f64 fallback.
                int m1 = 0x7F000000, m2 = 0x7F000000;
#pragma unroll
                for (int v = 0; v < NV; v++) {
                    float s = sa[v] + __ldg(&g_dlo2f[v][lj]);
                    int key = (__float_as_int(s) & 0xFFFFFFF0) | v;
                    int nm1 = min(m1, key);
                    m2 = min(m2, max(m1, key));
                    m1 = nm1;
                }
                int bv = m1 & 15;
                float s1 = __int_as_float(m1 & 0xFFFFFFF0);
                float s2 = __int_as_float(m2 & 0xFFFFFFF0);
                if (s2 - s1 < 1.0e-4f) {   // ambiguous -> exact f64 over all 12
                    double best = 1.0e300; bv = 0;
#pragma unroll
                    for (int v = 0; v < NV; v++) {
                        double s = __dadd_rn(g_dla2d[v][li], g_dlo2d[v][lj]);
                        if (s < best) { best = s; bv = v; }
                    }
                }
                int p = li * WW + lj;
                int j = p / HH;             // g2v = reshape(lon,lat).T scramble
                int i = p - j * HH;
                g_vmap[i * WW + j] = (unsigned char)bv;
            }
        }
    }

    barrier_all();     // g_vmap + g_nodes complete and visible

    // ================= Phase 3: all-chip scatter (write roofline) =================
    if (t < BB * NV * CC) s_sval[t] = g_nodes[t];
    __syncthreads();
    float4* out4 = reinterpret_cast<float4*>(out);
    const uchar4* vmap4 = reinterpret_cast<const uchar4*>(g_vmap);
    for (int u = bid; u < BB * SEGS; u += MEGA_BLOCKS) {
        int b = u / SEGS, seg = u - b * SEGS;
        int q = seg * 1024 + t;
        if (q < NQ4) {
            uchar4 vm = vmap4[q];
            const float* sv = s_sval + b * NV * CC;
#pragma unroll
            for (int c = 0; c < CC; c++) {
                float4 o;
                o.x = sv[vm.x * CC + c]; o.y = sv[vm.y * CC + c];
                o.z = sv[vm.z * CC + c]; o.w = sv[vm.w * CC + c];
                __stcs(&out4[(long)(b * CC + c) * NQ4 + q], o);
            }
        }
    }
}

extern "C" void kernel_launch(void* const* d_in, const int* in_sizes, int n_in,
                              void* d_out, int out_size) {
    const float* x        = (const float*)d_in[0];
    const float* W_in     = (const float*)d_in[2];
    const float* b_in     = (const float*)d_in[3];
    const float* W_layers = (const float*)d_in[4];
    const float* b_layers = (const float*)d_in[5];
    const float* W_out    = (const float*)d_in[6];
    const float* b_out    = (const float*)d_in[7];
    float* out = (float*)d_out;

    k_mega<<<MEGA_BLOCKS, 1024>>>(x, W_in, b_in, W_layers, b_layers, W_out, b_out, out);
}